// round 6
// baseline (speedup 1.0000x reference)
#include <cuda_runtime.h>

#define C 1604
#define NV4 401          // C / 4 vectors per row
#define BATCH 16384
#define EPS 1e-6f
#define ROW_THREADS 128

__device__ float g_row_loss[BATCH];

// exp(x) via FMA-pipe polynomial (keeps MUFU free). ~2e-7 relative error.
// n = rint(x/ln2) (magic-constant trick), r = x - n*ln2, exp(r) deg-6 Taylor,
// then exponent splice via integer add (ALU pipe).
__device__ __forceinline__ float fast_exp(float x) {
    x = fmaxf(x, -80.0f);                       // guard exponent underflow
    const float LOG2E = 1.4426950408889634f;
    const float LN2   = 0.6931471805599453f;
    float t  = x * LOG2E;
    float z  = t + 12582912.0f;                 // 1.5 * 2^23: round-to-nearest
    float nf = z - 12582912.0f;
    int   n  = __float_as_int(z) - 0x4B400000;  // integer part (two's complement in low bits)
    float r  = fmaf(-LN2, nf, x);               // r in [-0.3466, 0.3466]
    float p  = 1.3888889e-3f;                   // 1/720
    p = fmaf(p, r, 8.3333333e-3f);              // 1/120
    p = fmaf(p, r, 4.1666667e-2f);              // 1/24
    p = fmaf(p, r, 1.6666667e-1f);              // 1/6
    p = fmaf(p, r, 0.5f);
    p = fmaf(p, r, 1.0f);
    p = fmaf(p, r, 1.0f);
    return __int_as_float(__float_as_int(p) + (n << 23));
}

__global__ void __launch_bounds__(ROW_THREADS)
seesaw_row_kernel(const float* __restrict__ logits,
                  const float* __restrict__ s,
                  const int*   __restrict__ targets) {
    const int b    = blockIdx.x;
    const int tid  = threadIdx.x;
    const int lane = tid & 31;
    const int wid  = tid >> 5;

    const float4* lrow = reinterpret_cast<const float4*>(logits + (size_t)b * C);

    // Load full row into registers (4 float4 slots, last iteration partial).
    float4 v[4];
    float mx = -1e30f;
#pragma unroll
    for (int k = 0; k < 4; k++) {
        int j = tid + k * ROW_THREADS;
        if (j < NV4) {
            v[k] = lrow[j];
            mx = fmaxf(mx, fmaxf(fmaxf(v[k].x, v[k].y), fmaxf(v[k].z, v[k].w)));
        }
    }

    // Row max: warp shuffle reduce, then cross-warp via smem.
#pragma unroll
    for (int off = 16; off; off >>= 1)
        mx = fmaxf(mx, __shfl_xor_sync(0xFFFFFFFFu, mx, off));
    __shared__ float smax[4];
    __shared__ float ssum[4];
    if (lane == 0) smax[wid] = mx;
    __syncthreads();
    mx = fmaxf(fmaxf(smax[0], smax[1]), fmaxf(smax[2], smax[3]));

    // Gathered dot: denom_partial = sum_j s[tgt, j] * exp(l[j] - mx)
    const int tgt = targets[b];
    const float4* srow = reinterpret_cast<const float4*>(s + (size_t)tgt * C);
    float acc = 0.0f;
#pragma unroll
    for (int k = 0; k < 4; k++) {
        int j = tid + k * ROW_THREADS;
        if (j < NV4) {
            float4 sv = srow[j];
            acc = fmaf(sv.x, fast_exp(v[k].x - mx), acc);
            acc = fmaf(sv.y, fast_exp(v[k].y - mx), acc);
            acc = fmaf(sv.z, fast_exp(v[k].z - mx), acc);
            acc = fmaf(sv.w, fast_exp(v[k].w - mx), acc);
        }
    }
#pragma unroll
    for (int off = 16; off; off >>= 1)
        acc += __shfl_xor_sync(0xFFFFFFFFu, acc, off);
    if (lane == 0) ssum[wid] = acc;
    __syncthreads();

    if (tid == 0) {
        float denom = ssum[0] + ssum[1] + ssum[2] + ssum[3];
        float lt    = logits[(size_t)b * C + tgt];
        float numer = fast_exp(lt - mx);
        float stt   = s[(size_t)tgt * C + tgt];
        denom += (1.0f - stt) * numer;      // exact diagonal handling (ref uses coeff 1, not s[t,t])
        float sigma = numer / (denom + EPS);
        g_row_loss[b] = -logf(sigma + EPS);
    }
}

__global__ void __launch_bounds__(256)
seesaw_reduce_kernel(float* __restrict__ out) {
    const int tid  = threadIdx.x;
    const int lane = tid & 31;
    const int wid  = tid >> 5;
    float acc = 0.0f;
    for (int i = tid; i < BATCH; i += 256)
        acc += g_row_loss[i];
#pragma unroll
    for (int off = 16; off; off >>= 1)
        acc += __shfl_xor_sync(0xFFFFFFFFu, acc, off);
    __shared__ float sred[8];
    if (lane == 0) sred[wid] = acc;
    __syncthreads();
    if (tid == 0) {
        float total = 0.0f;
#pragma unroll
        for (int w = 0; w < 8; w++) total += sred[w];
        out[0] = total * (1.0f / (float)BATCH);
    }
}

extern "C" void kernel_launch(void* const* d_in, const int* in_sizes, int n_in,
                              void* d_out, int out_size) {
    const float* logits  = (const float*)d_in[0];
    const float* s       = (const float*)d_in[1];
    const int*   targets = (const int*)d_in[2];
    float*       out     = (float*)d_out;

    seesaw_row_kernel<<<BATCH, ROW_THREADS>>>(logits, s, targets);
    seesaw_reduce_kernel<<<1, 256>>>(out);
}